// round 6
// baseline (speedup 1.0000x reference)
#include <cuda_runtime.h>
#include <cuda_bf16.h>
#include <cstdint>

#define NPTS   200000
#define CIN    64
#define COUT   16
#define SXD    998
#define SYD    998
#define SZD    38
#define YZ     37924          /* SYD*SZD */
#define SENTV  37848152u
#define NKTOT  5400000        /* NPTS*27 */
#define WORDS  1182755
#define CHUNK  4096
#define NPART  289
#define WPAD   (NPART*CHUNK)
#define ZBLK   (WPAD/1024)
#define FOB    512

#define NOUT   432            /* 27*16 */
#define BSTR   72             /* padded row stride (bf16 elems) = 144B */
#define TILEM  256
#define NCTA   782            /* ceil(200000/256) */

/* smem layout (bytes) */
#define AH_OFF   0            /* 256*144 = 36864 */
#define AL_OFF   36864
#define BH_OFF   73728        /* 432*144 = 62208 */
#define BL_OFF   135936
#define EPI_OFF  198144       /* 8 warps * 2048 */
#define SMEM_SZ  214528

// ---------------- device scratch ----------------
__device__ __align__(16) unsigned g_bitmap[WPAD];
__device__ __align__(16) unsigned g_coll[WPAD];
__device__ __align__(16) unsigned g_pref[WPAD];
__device__ __align__(16) unsigned short g_Bh[NOUT * BSTR];
__device__ __align__(16) unsigned short g_Bl[NOUT * BSTR];
__device__ unsigned g_part[NPART];
__device__ unsigned g_M;

static __device__ __forceinline__ uint32_t smem_u32(const void* p) {
    uint32_t a;
    asm("{ .reg .u64 t; cvta.to.shared.u64 t, %1; cvt.u32.u64 %0, t; }" : "=r"(a) : "l"(p));
    return a;
}

#define MMA(C, A, b0v, b1v) \
    asm volatile("mma.sync.aligned.m16n8k16.row.col.f32.bf16.bf16.f32 " \
        "{%0,%1,%2,%3},{%4,%5,%6,%7},{%8,%9},{%0,%1,%2,%3};" \
        : "+f"((C)[0]), "+f"((C)[1]), "+f"((C)[2]), "+f"((C)[3]) \
        : "r"((A)[0]), "r"((A)[1]), "r"((A)[2]), "r"((A)[3]), "r"(b0v), "r"(b1v))

// ---------------- kernels ----------------
// zero both bitmaps + build padded bf16 hi/lo B [og][c]
__global__ void k_zero(const float* __restrict__ W) {
    if (blockIdx.x < 2 * ZBLK) {
        unsigned* dst = (blockIdx.x < ZBLK) ? g_bitmap : g_coll;
        unsigned b = (blockIdx.x < ZBLK) ? blockIdx.x : blockIdx.x - ZBLK;
        unsigned i = b * 1024 + threadIdx.x * 4;
        *reinterpret_cast<uint4*>(&dst[i]) = make_uint4(0u, 0u, 0u, 0u);
    } else {
        int k = blockIdx.x - 2 * ZBLK;
#pragma unroll
        for (int u = 0; u < 4; u++) {
            int idx = threadIdx.x + u * 256;
            int o = idx >> 6, c = idx & 63;
            float v = W[k * 1024 + c * 16 + o];
            __nv_bfloat16 h = __float2bfloat16(v);
            __nv_bfloat16 l = __float2bfloat16(v - __bfloat162float(h));
            int og = k * 16 + o;
            g_Bh[og * BSTR + c] = reinterpret_cast<unsigned short&>(h);
            g_Bl[og * BSTR + c] = reinterpret_cast<unsigned short&>(l);
        }
    }
}

__global__ void k_mark(const int4* __restrict__ coords) {
    int n = blockIdx.x * blockDim.x + threadIdx.x;
    if (n >= NPTS) return;
    int4 c = coords[n];
#pragma unroll
    for (int k = 0; k < 27; k++) {
        int ox = c.y - k / 9;
        int oy = c.z - (k / 3) % 3;
        int oz = c.w - k % 3;
        if ((unsigned)ox < SXD && (unsigned)oy < SYD && (unsigned)oz < SZD) {
            unsigned lin = (unsigned)ox * YZ + (unsigned)oy * SZD + (unsigned)oz;
            unsigned bit = 1u << (lin & 31);
            unsigned old = atomicOr(&g_bitmap[lin >> 5], bit);
            if (old & bit) atomicOr(&g_coll[lin >> 5], bit);
        }
    }
}

__global__ void k_scan1() {
    __shared__ unsigned sh[256];
    unsigned base = blockIdx.x * CHUNK + threadIdx.x * 16;
    unsigned s = 0;
#pragma unroll
    for (int i = 0; i < 16; i += 4) {
        uint4 v = *reinterpret_cast<const uint4*>(&g_bitmap[base + i]);
        s += __popc(v.x) + __popc(v.y) + __popc(v.z) + __popc(v.w);
    }
    sh[threadIdx.x] = s;
    __syncthreads();
    for (int off = 128; off > 0; off >>= 1) {
        if (threadIdx.x < (unsigned)off) sh[threadIdx.x] += sh[threadIdx.x + off];
        __syncthreads();
    }
    if (threadIdx.x == 0) g_part[blockIdx.x] = sh[0];
}

__global__ void k_scan2() {
    __shared__ unsigned sh[512];
    unsigned t = threadIdx.x;
    unsigned v = (t < NPART) ? g_part[t] : 0u;
    sh[t] = v;
    __syncthreads();
    for (int off = 1; off < 512; off <<= 1) {
        unsigned add = (t >= (unsigned)off) ? sh[t - off] : 0u;
        __syncthreads();
        sh[t] += add;
        __syncthreads();
    }
    if (t < NPART) g_part[t] = sh[t] - v;
    if (t == NPART - 1) g_M = sh[t];
}

// combo: blocks [0,NPART): per-word prefix + emit uniq + bias-init collision rows;
//        remaining blocks: zero tail rows (j>=M) + SENT-pad uniq
__global__ void k_combo(float4* __restrict__ out4, const float4* __restrict__ bias4,
                        float* __restrict__ uniqf) {
    float4 bsv[4];
#pragma unroll
    for (int j = 0; j < 4; j++) bsv[j] = __ldg(&bias4[j]);

    if (blockIdx.x < NPART) {
        __shared__ unsigned sh[256];
        unsigned base = blockIdx.x * CHUNK + threadIdx.x * 16;
        unsigned w[16];
#pragma unroll
        for (int i = 0; i < 16; i += 4)
            *reinterpret_cast<uint4*>(&w[i]) = *reinterpret_cast<const uint4*>(&g_bitmap[base + i]);
        unsigned s = 0;
#pragma unroll
        for (int i = 0; i < 16; i++) s += __popc(w[i]);
        sh[threadIdx.x] = s;
        __syncthreads();
        for (int off = 1; off < 256; off <<= 1) {
            unsigned add = (threadIdx.x >= (unsigned)off) ? sh[threadIdx.x - off] : 0u;
            __syncthreads();
            sh[threadIdx.x] += add;
            __syncthreads();
        }
        unsigned run = g_part[blockIdx.x] + (sh[threadIdx.x] - s);
#pragma unroll 1
        for (int i = 0; i < 16; i++) {
            g_pref[base + i] = run;
            unsigned bits = w[i];
            if (bits) {
                unsigned collw = g_coll[base + i];
                unsigned vb = (base + i) << 5;
                unsigned r = run;
                run += __popc(bits);
                while (bits) {
                    unsigned b = __ffs(bits) - 1u;
                    bits &= bits - 1u;
                    uniqf[r] = (float)(vb + b);
                    if ((collw >> b) & 1u) {
                        float4* o = out4 + (size_t)r * 4;
                        o[0] = bsv[0]; o[1] = bsv[1]; o[2] = bsv[2]; o[3] = bsv[3];
                    }
                    r++;
                }
            }
        }
    } else {
        unsigned b = blockIdx.x - NPART;
        unsigned stride = (gridDim.x - NPART) * 256u;
        unsigned M = g_M;
        const float4 z4 = make_float4(0.f, 0.f, 0.f, 0.f);
        for (unsigned i = b * 256u + threadIdx.x; i < (unsigned)NKTOT * 4u; i += stride) {
            unsigned j = i >> 2;
            if (j >= M) out4[i] = z4;
        }
        for (unsigned j = b * 256u + threadIdx.x; j < (unsigned)NKTOT; j += stride)
            if (j >= M) uniqf[j] = 37848152.0f;
    }
}

// ---------------- HMMA GEMM + collision-split scatter ----------------
__global__ void __launch_bounds__(256, 1) k_gemm(
    const float4* __restrict__ feats4, const int4* __restrict__ coords,
    float* __restrict__ out, const float4* __restrict__ bias4)
{
    extern __shared__ char smem[];
    uint32_t sb = smem_u32(smem);
    int tid = threadIdx.x;
    int wid = tid >> 5;
    int lane = tid & 31;
    int base_n = blockIdx.x * TILEM;

    // stage B hi/lo
    {
        const uint4* bh = reinterpret_cast<const uint4*>(g_Bh);
        const uint4* bl = reinterpret_cast<const uint4*>(g_Bl);
        uint4* dh = reinterpret_cast<uint4*>(smem + BH_OFF);
        uint4* dl = reinterpret_cast<uint4*>(smem + BL_OFF);
        for (int i = tid; i < 3888; i += 256) {
            dh[i] = __ldg(&bh[i]);
            dl[i] = __ldg(&bl[i]);
        }
    }
    // stage A tile as bf16 hi/lo
    for (int i = tid; i < 4096; i += 256) {
        int r = i >> 4, col = i & 15;
        int n = base_n + r;
        float4 f = (n < NPTS) ? __ldg(&feats4[(size_t)n * 16 + col])
                              : make_float4(0.f, 0.f, 0.f, 0.f);
        __nv_bfloat16 h0 = __float2bfloat16(f.x), h1 = __float2bfloat16(f.y);
        __nv_bfloat16 h2 = __float2bfloat16(f.z), h3 = __float2bfloat16(f.w);
        __nv_bfloat16 l0 = __float2bfloat16(f.x - __bfloat162float(h0));
        __nv_bfloat16 l1 = __float2bfloat16(f.y - __bfloat162float(h1));
        __nv_bfloat16 l2 = __float2bfloat16(f.z - __bfloat162float(h2));
        __nv_bfloat16 l3 = __float2bfloat16(f.w - __bfloat162float(h3));
        uint2 hv, lv;
        hv.x = (unsigned)reinterpret_cast<unsigned short&>(h0) |
               ((unsigned)reinterpret_cast<unsigned short&>(h1) << 16);
        hv.y = (unsigned)reinterpret_cast<unsigned short&>(h2) |
               ((unsigned)reinterpret_cast<unsigned short&>(h3) << 16);
        lv.x = (unsigned)reinterpret_cast<unsigned short&>(l0) |
               ((unsigned)reinterpret_cast<unsigned short&>(l1) << 16);
        lv.y = (unsigned)reinterpret_cast<unsigned short&>(l2) |
               ((unsigned)reinterpret_cast<unsigned short&>(l3) << 16);
        unsigned off = (unsigned)r * 144u + (unsigned)col * 8u;
        *reinterpret_cast<uint2*>(smem + AH_OFF + off) = hv;
        *reinterpret_cast<uint2*>(smem + AL_OFF + off) = lv;
    }
    __syncthreads();

    // per-warp A fragments
    int warpRow = wid * 32;
    uint32_t ah[2][4][4], al[2][4][4];
    {
        uint32_t abase = sb + AH_OFF + (unsigned)(warpRow + (lane & 15)) * 144u
                       + ((unsigned)(lane >> 4) & 1u) * 16u;
#pragma unroll
        for (int rg = 0; rg < 2; rg++) {
#pragma unroll
            for (int ks = 0; ks < 4; ks++) {
                uint32_t a0 = abase + rg * (16u * 144u) + ks * 32u;
                asm volatile("ldmatrix.sync.aligned.m8n8.x4.shared.b16 {%0,%1,%2,%3},[%4];"
                    : "=r"(ah[rg][ks][0]), "=r"(ah[rg][ks][1]),
                      "=r"(ah[rg][ks][2]), "=r"(ah[rg][ks][3]) : "r"(a0));
                uint32_t a1 = a0 + (AL_OFF - AH_OFF);
                asm volatile("ldmatrix.sync.aligned.m8n8.x4.shared.b16 {%0,%1,%2,%3},[%4];"
                    : "=r"(al[rg][ks][0]), "=r"(al[rg][ks][1]),
                      "=r"(al[rg][ks][2]), "=r"(al[rg][ks][3]) : "r"(a1));
            }
        }
    }

    int myn = base_n + warpRow + lane;
    bool pv = (myn < NPTS);
    int4 cc = coords[pv ? myn : 0];
    float4 bq = __ldg(&bias4[lane & 3]);      // bias quarter for this lane's q

    uint32_t bl_lane = (unsigned)(lane & 7) * 144u + ((unsigned)(lane >> 3) & 1u) * 16u;
    char* ebuf = smem + EPI_OFF + wid * 2048;

#pragma unroll 1
    for (int k = 0; k < 27; k++) {
        // rank for this lane's row at offset k (bit31 = collision)
        unsigned rank = 0xFFFFFFFFu;
        {
            int ox = cc.y - k / 9;
            int oy = cc.z - (k / 3) % 3;
            int oz = cc.w - k % 3;
            if (pv && (unsigned)ox < SXD && (unsigned)oy < SYD && (unsigned)oz < SZD) {
                unsigned lin = (unsigned)ox * YZ + (unsigned)oy * SZD + (unsigned)oz;
                unsigned word = lin >> 5;
                unsigned bpos = lin & 31;
                rank = __ldg(&g_pref[word]) +
                       __popc(__ldg(&g_bitmap[word]) & ((1u << bpos) - 1u));
                if ((__ldg(&g_coll[word]) >> bpos) & 1u) rank |= 0x80000000u;
            }
        }

        float c[2][2][4];
#pragma unroll
        for (int rg = 0; rg < 2; rg++)
#pragma unroll
            for (int n2 = 0; n2 < 2; n2++)
#pragma unroll
                for (int q = 0; q < 4; q++) c[rg][n2][q] = 0.f;

        uint32_t bk = (unsigned)(k * 16) * 144u + bl_lane;
#pragma unroll
        for (int pass = 0; pass < 3; pass++) {
            uint32_t boff = sb + ((pass == 1) ? BL_OFF : BH_OFF) + bk;
#pragma unroll
            for (int kk = 0; kk < 4; kk++) {
#pragma unroll
                for (int n2 = 0; n2 < 2; n2++) {
                    uint32_t b0, b1;
                    uint32_t ba = boff + (unsigned)(n2 * 8) * 144u + (unsigned)kk * 32u;
                    asm volatile("ldmatrix.sync.aligned.m8n8.x2.shared.b16 {%0,%1},[%2];"
                                 : "=r"(b0), "=r"(b1) : "r"(ba));
                    if (pass == 2) {
                        MMA(c[0][n2], al[0][kk], b0, b1);
                        MMA(c[1][n2], al[1][kk], b0, b1);
                    } else {
                        MMA(c[0][n2], ah[0][kk], b0, b1);
                        MMA(c[1][n2], ah[1][kk], b0, b1);
                    }
                }
            }
        }

        __syncwarp();
        {
            int r0 = (lane >> 2);
            int cb = (lane & 3) * 2;
#pragma unroll
            for (int rg = 0; rg < 2; rg++) {
#pragma unroll
                for (int n2 = 0; n2 < 2; n2++) {
                    int colb = n2 * 8 + cb;
                    *reinterpret_cast<float2*>(ebuf + (rg * 16 + r0) * 64 + colb * 4) =
                        make_float2(c[rg][n2][0], c[rg][n2][1]);
                    *reinterpret_cast<float2*>(ebuf + (rg * 16 + r0 + 8) * 64 + colb * 4) =
                        make_float2(c[rg][n2][2], c[rg][n2][3]);
                }
            }
        }
        __syncwarp();
#pragma unroll
        for (int j = 0; j < 4; j++) {
            int rw = j * 8 + (lane >> 2);
            int q = lane & 3;
            unsigned rr = __shfl_sync(0xffffffffu, rank, rw);
            if (rr != 0xFFFFFFFFu) {
                float4 v = *reinterpret_cast<const float4*>(ebuf + rw * 64 + q * 16);
                if (rr & 0x80000000u) {
                    asm volatile("red.global.add.v4.f32 [%0], {%1,%2,%3,%4};"
                                 :: "l"(out + (size_t)(rr & 0x7FFFFFFFu) * 16 + q * 4),
                                    "f"(v.x), "f"(v.y), "f"(v.z), "f"(v.w)
                                 : "memory");
                } else {
                    float4 w = make_float4(v.x + bq.x, v.y + bq.y, v.z + bq.z, v.w + bq.w);
                    *reinterpret_cast<float4*>(out + (size_t)rr * 16 + q * 4) = w;
                }
            }
        }
    }
}

// ---------------- launch ----------------
extern "C" void kernel_launch(void* const* d_in, const int* in_sizes, int n_in,
                              void* d_out, int out_size) {
    const float* feats = (const float*)d_in[0];
    const int*   coords = (const int*)d_in[1];
    const float* W = (const float*)d_in[2];
    const float* bias = (const float*)d_in[3];
    float* out = (float*)d_out;
    float* uniqf = out + (size_t)NKTOT * 16;

    cudaFuncSetAttribute(k_gemm, cudaFuncAttributeMaxDynamicSharedMemorySize, SMEM_SZ);

    k_zero<<<2 * ZBLK + 27, 256>>>(W);
    k_mark<<<(NPTS + 255) / 256, 256>>>((const int4*)coords);
    k_scan1<<<NPART, 256>>>();
    k_scan2<<<1, 512>>>();
    k_combo<<<NPART + FOB, 256>>>((float4*)out, (const float4*)bias, uniqf);
    k_gemm<<<NCTA, 256, SMEM_SZ>>>((const float4*)feats, (const int4*)coords,
                                   out, (const float4*)bias);
}

// round 7
// speedup vs baseline: 1.2429x; 1.2429x over previous
#include <cuda_runtime.h>
#include <cuda_bf16.h>
#include <cstdint>

#define NPTS   200000
#define CIN    64
#define COUT   16
#define SXD    998
#define SYD    998
#define SZD    38
#define YZ     37924          /* SYD*SZD */
#define SENTV  37848152u
#define NKTOT  5400000        /* NPTS*27 */
#define WORDS  1182755
#define CHUNK  4096
#define NPART  289
#define WPAD   (NPART*CHUNK)
#define ZBLK   (WPAD/1024)
#define FOB    2048

#define NOUT   432            /* 27*16 */
#define BSTR   72             /* padded row stride (bf16 elems) = 144B */
#define TILEM  128
#define NT     1563           /* ceil(200000/128) */
#define KSPL   2
#define KB0    14             /* k split: [0,14) and [14,27) */

/* smem layout (bytes) */
#define AH_OFF   0            /* 128*144 = 18432 */
#define AL_OFF   18432
#define BH_OFF   36864        /* 224*144 = 32256 max */
#define BL_OFF   69120
#define SMEM_SZ  101376       /* <112KB -> 2 CTAs/SM */

// ---------------- device scratch ----------------
__device__ __align__(16) unsigned g_bitmap[WPAD];
__device__ __align__(16) unsigned g_pref[WPAD];
__device__ __align__(16) unsigned g_rank[27 * NPTS];
__device__ __align__(16) unsigned short g_Bh[NOUT * BSTR];
__device__ __align__(16) unsigned short g_Bl[NOUT * BSTR];
__device__ unsigned g_part[NPART];
__device__ unsigned g_M;

static __device__ __forceinline__ uint32_t smem_u32(const void* p) {
    uint32_t a;
    asm("{ .reg .u64 t; cvta.to.shared.u64 t, %1; cvt.u32.u64 %0, t; }" : "=r"(a) : "l"(p));
    return a;
}

#define MMA(C, A, b0v, b1v) \
    asm volatile("mma.sync.aligned.m16n8k16.row.col.f32.bf16.bf16.f32 " \
        "{%0,%1,%2,%3},{%4,%5,%6,%7},{%8,%9},{%0,%1,%2,%3};" \
        : "+f"((C)[0]), "+f"((C)[1]), "+f"((C)[2]), "+f"((C)[3]) \
        : "r"((A)[0]), "r"((A)[1]), "r"((A)[2]), "r"((A)[3]), "r"(b0v), "r"(b1v))

// ---------------- kernels ----------------
__global__ void k_zero(const float* __restrict__ W) {
    if (blockIdx.x < ZBLK) {
        unsigned i = blockIdx.x * 1024 + threadIdx.x * 4;
        *reinterpret_cast<uint4*>(&g_bitmap[i]) = make_uint4(0u, 0u, 0u, 0u);
    } else {
        int k = blockIdx.x - ZBLK;
#pragma unroll
        for (int u = 0; u < 4; u++) {
            int idx = threadIdx.x + u * 256;
            int o = idx >> 6, c = idx & 63;
            float v = W[k * 1024 + c * 16 + o];
            __nv_bfloat16 h = __float2bfloat16(v);
            __nv_bfloat16 l = __float2bfloat16(v - __bfloat162float(h));
            int og = k * 16 + o;
            g_Bh[og * BSTR + c] = reinterpret_cast<unsigned short&>(h);
            g_Bl[og * BSTR + c] = reinterpret_cast<unsigned short&>(l);
        }
    }
}

__global__ void k_mark(const int4* __restrict__ coords) {
    int n = blockIdx.x * blockDim.x + threadIdx.x;
    if (n >= NPTS) return;
    int4 c = coords[n];
#pragma unroll
    for (int k = 0; k < 27; k++) {
        int ox = c.y - k / 9;
        int oy = c.z - (k / 3) % 3;
        int oz = c.w - k % 3;
        if ((unsigned)ox < SXD && (unsigned)oy < SYD && (unsigned)oz < SZD) {
            unsigned lin = (unsigned)ox * YZ + (unsigned)oy * SZD + (unsigned)oz;
            atomicOr(&g_bitmap[lin >> 5], 1u << (lin & 31));
        }
    }
}

__global__ void k_scan1() {
    __shared__ unsigned sh[256];
    unsigned base = blockIdx.x * CHUNK + threadIdx.x * 16;
    unsigned s = 0;
#pragma unroll
    for (int i = 0; i < 16; i += 4) {
        uint4 v = *reinterpret_cast<const uint4*>(&g_bitmap[base + i]);
        s += __popc(v.x) + __popc(v.y) + __popc(v.z) + __popc(v.w);
    }
    sh[threadIdx.x] = s;
    __syncthreads();
    for (int off = 128; off > 0; off >>= 1) {
        if (threadIdx.x < (unsigned)off) sh[threadIdx.x] += sh[threadIdx.x + off];
        __syncthreads();
    }
    if (threadIdx.x == 0) g_part[blockIdx.x] = sh[0];
}

__global__ void k_scan2() {
    __shared__ unsigned sh[512];
    unsigned t = threadIdx.x;
    unsigned v = (t < NPART) ? g_part[t] : 0u;
    sh[t] = v;
    __syncthreads();
    for (int off = 1; off < 512; off <<= 1) {
        unsigned add = (t >= (unsigned)off) ? sh[t - off] : 0u;
        __syncthreads();
        sh[t] += add;
        __syncthreads();
    }
    if (t < NPART) g_part[t] = sh[t] - v;
    if (t == NPART - 1) g_M = sh[t];
}

// combo: blocks [0,NPART): per-word prefix; rest: bias init + SENT pad
__global__ void k_combo(float4* __restrict__ out4, const float4* __restrict__ bias4,
                        float* __restrict__ uniqf) {
    if (blockIdx.x < NPART) {
        __shared__ unsigned sh[256];
        unsigned base = blockIdx.x * CHUNK + threadIdx.x * 16;
        unsigned w[16];
#pragma unroll
        for (int i = 0; i < 16; i += 4)
            *reinterpret_cast<uint4*>(&w[i]) = *reinterpret_cast<const uint4*>(&g_bitmap[base + i]);
        unsigned s = 0;
#pragma unroll
        for (int i = 0; i < 16; i++) s += __popc(w[i]);
        sh[threadIdx.x] = s;
        __syncthreads();
        for (int off = 1; off < 256; off <<= 1) {
            unsigned add = (threadIdx.x >= (unsigned)off) ? sh[threadIdx.x - off] : 0u;
            __syncthreads();
            sh[threadIdx.x] += add;
            __syncthreads();
        }
        unsigned run = g_part[blockIdx.x] + (sh[threadIdx.x] - s);
#pragma unroll
        for (int i = 0; i < 16; i++) {
            g_pref[base + i] = run;
            run += __popc(w[i]);
        }
    } else {
        unsigned b = blockIdx.x - NPART;
        unsigned stride = (gridDim.x - NPART) * 256u;
        unsigned M = g_M;
        float4 bsv[4];
#pragma unroll
        for (int j = 0; j < 4; j++) bsv[j] = __ldg(&bias4[j]);
        const float4 z4 = make_float4(0.f, 0.f, 0.f, 0.f);
        for (unsigned i = b * 256u + threadIdx.x; i < (unsigned)NKTOT * 4u; i += stride) {
            unsigned j = i >> 2;
            out4[i] = (j < M) ? bsv[i & 3u] : z4;
        }
        for (unsigned j = b * 256u + threadIdx.x; j < (unsigned)NKTOT; j += stride)
            if (j >= M) uniqf[j] = 37848152.0f;
    }
}

// precompute rank[k][n] (0xFFFFFFFF = invalid)
__global__ void k_rank(const int4* __restrict__ coords) {
    int n = blockIdx.x * blockDim.x + threadIdx.x;
    if (n >= NPTS) return;
    int4 c = coords[n];
#pragma unroll
    for (int k = 0; k < 27; k++) {
        int ox = c.y - k / 9;
        int oy = c.z - (k / 3) % 3;
        int oz = c.w - k % 3;
        unsigned rank = 0xFFFFFFFFu;
        if ((unsigned)ox < SXD && (unsigned)oy < SYD && (unsigned)oz < SZD) {
            unsigned lin = (unsigned)ox * YZ + (unsigned)oy * SZD + (unsigned)oz;
            unsigned word = lin >> 5;
            rank = __ldg(&g_pref[word]) +
                   __popc(__ldg(&g_bitmap[word]) & ((1u << (lin & 31)) - 1u));
        }
        g_rank[k * NPTS + n] = rank;
    }
}

__global__ void k_emit(float* __restrict__ uniqf) {
    unsigned i = blockIdx.x * blockDim.x + threadIdx.x;
    if (i >= WORDS) return;
    unsigned bits = g_bitmap[i];
    if (!bits) return;
    unsigned r = g_pref[i];
    unsigned vbase = i << 5;
    while (bits) {
        unsigned b = __ffs(bits) - 1u;
        bits &= bits - 1u;
        uniqf[r++] = (float)(vbase + b);
    }
}

// ---------------- HMMA GEMM + fused scatter (k-split, 2 CTA/SM) ----------------
__global__ void __launch_bounds__(256, 2) k_gemm(
    const float4* __restrict__ feats4, float* __restrict__ out)
{
    extern __shared__ char smem[];
    uint32_t sb = smem_u32(smem);
    int tid = threadIdx.x;
    int wid = tid >> 5;
    int lane = tid & 31;
    int tile = blockIdx.x >> 1;
    int khalf = blockIdx.x & 1;
    int kbeg = khalf ? KB0 : 0;
    int kend = khalf ? 27 : KB0;
    int base_n = tile * TILEM;

    // stage B hi/lo for our k-range
    {
        int nu4 = (kend - kbeg) * 144;         // 144 uint4 per k (16 rows * 144B)
        const uint4* bh = reinterpret_cast<const uint4*>(g_Bh) + kbeg * 144;
        const uint4* bl = reinterpret_cast<const uint4*>(g_Bl) + kbeg * 144;
        uint4* dh = reinterpret_cast<uint4*>(smem + BH_OFF);
        uint4* dl = reinterpret_cast<uint4*>(smem + BL_OFF);
        for (int i = tid; i < nu4; i += 256) {
            dh[i] = __ldg(&bh[i]);
            dl[i] = __ldg(&bl[i]);
        }
    }
    // stage A tile (128 rows) as bf16 hi/lo
    for (int i = tid; i < 2048; i += 256) {    // 128 rows x 16 float4
        int r = i >> 4, col = i & 15;
        int n = base_n + r;
        float4 f = (n < NPTS) ? __ldg(&feats4[(size_t)n * 16 + col])
                              : make_float4(0.f, 0.f, 0.f, 0.f);
        __nv_bfloat16 h0 = __float2bfloat16(f.x), h1 = __float2bfloat16(f.y);
        __nv_bfloat16 h2 = __float2bfloat16(f.z), h3 = __float2bfloat16(f.w);
        __nv_bfloat16 l0 = __float2bfloat16(f.x - __bfloat162float(h0));
        __nv_bfloat16 l1 = __float2bfloat16(f.y - __bfloat162float(h1));
        __nv_bfloat16 l2 = __float2bfloat16(f.z - __bfloat162float(h2));
        __nv_bfloat16 l3 = __float2bfloat16(f.w - __bfloat162float(h3));
        uint2 hv, lv;
        hv.x = (unsigned)reinterpret_cast<unsigned short&>(h0) |
               ((unsigned)reinterpret_cast<unsigned short&>(h1) << 16);
        hv.y = (unsigned)reinterpret_cast<unsigned short&>(h2) |
               ((unsigned)reinterpret_cast<unsigned short&>(h3) << 16);
        lv.x = (unsigned)reinterpret_cast<unsigned short&>(l0) |
               ((unsigned)reinterpret_cast<unsigned short&>(l1) << 16);
        lv.y = (unsigned)reinterpret_cast<unsigned short&>(l2) |
               ((unsigned)reinterpret_cast<unsigned short&>(l3) << 16);
        unsigned off = (unsigned)r * 144u + (unsigned)col * 8u;
        *reinterpret_cast<uint2*>(smem + AH_OFF + off) = hv;
        *reinterpret_cast<uint2*>(smem + AL_OFF + off) = lv;
    }
    __syncthreads();

    // per-warp A fragments (16 rows)
    uint32_t ah[4][4], al[4][4];
    {
        uint32_t abase = sb + AH_OFF + (unsigned)(wid * 16 + (lane & 15)) * 144u
                       + ((unsigned)(lane >> 4) & 1u) * 16u;
#pragma unroll
        for (int kk = 0; kk < 4; kk++) {
            uint32_t a0 = abase + kk * 32u;
            asm volatile("ldmatrix.sync.aligned.m8n8.x4.shared.b16 {%0,%1,%2,%3},[%4];"
                : "=r"(ah[kk][0]), "=r"(ah[kk][1]), "=r"(ah[kk][2]), "=r"(ah[kk][3]) : "r"(a0));
            uint32_t a1 = a0 + (AL_OFF - AH_OFF);
            asm volatile("ldmatrix.sync.aligned.m8n8.x4.shared.b16 {%0,%1,%2,%3},[%4];"
                : "=r"(al[kk][0]), "=r"(al[kk][1]), "=r"(al[kk][2]), "=r"(al[kk][3]) : "r"(a1));
        }
    }
    __syncthreads();                            // A smem now free -> reuse as ebuf

    char* ebuf = smem + wid * 1024;             // 16 rows x 64B
    uint32_t bl_lane = (unsigned)(lane & 7) * 144u + ((unsigned)(lane >> 3) & 1u) * 16u;

#pragma unroll 1
    for (int k = kbeg; k < kend; k++) {
        // coalesced rank load (lanes 0..15 hold rows)
        unsigned rank = 0xFFFFFFFFu;
        if (lane < 16)
            rank = __ldg(&g_rank[(size_t)k * NPTS + base_n + wid * 16 + lane]);

        // B fragments for this k (hi + lo), loaded once
        uint32_t bh[4][2][2], blo[4][2][2];
        uint32_t bk = sb + (unsigned)(k - kbeg) * 2304u + bl_lane;
#pragma unroll
        for (int kk = 0; kk < 4; kk++) {
#pragma unroll
            for (int n2 = 0; n2 < 2; n2++) {
                uint32_t ba = bk + (unsigned)(n2 * 8) * 144u + (unsigned)kk * 32u;
                asm volatile("ldmatrix.sync.aligned.m8n8.x2.shared.b16 {%0,%1},[%2];"
                             : "=r"(bh[kk][n2][0]), "=r"(bh[kk][n2][1])
                             : "r"(ba + BH_OFF));
                asm volatile("ldmatrix.sync.aligned.m8n8.x2.shared.b16 {%0,%1},[%2];"
                             : "=r"(blo[kk][n2][0]), "=r"(blo[kk][n2][1])
                             : "r"(ba + BL_OFF));
            }
        }

        float c[2][4];
#pragma unroll
        for (int n2 = 0; n2 < 2; n2++)
#pragma unroll
            for (int q = 0; q < 4; q++) c[n2][q] = 0.f;

#pragma unroll
        for (int kk = 0; kk < 4; kk++) {
#pragma unroll
            for (int n2 = 0; n2 < 2; n2++) {
                MMA(c[n2], ah[kk], bh[kk][n2][0], bh[kk][n2][1]);
                MMA(c[n2], al[kk], bh[kk][n2][0], bh[kk][n2][1]);
                MMA(c[n2], ah[kk], blo[kk][n2][0], blo[kk][n2][1]);
            }
        }

        __syncwarp();
        {
            int r0 = lane >> 2;
            int cb = (lane & 3) * 2;
#pragma unroll
            for (int n2 = 0; n2 < 2; n2++) {
                int colb = n2 * 8 + cb;
                *reinterpret_cast<float2*>(ebuf + r0 * 64 + colb * 4) =
                    make_float2(c[n2][0], c[n2][1]);
                *reinterpret_cast<float2*>(ebuf + (r0 + 8) * 64 + colb * 4) =
                    make_float2(c[n2][2], c[n2][3]);
            }
        }
        __syncwarp();
#pragma unroll
        for (int j = 0; j < 2; j++) {
            int rw = j * 8 + (lane >> 2);
            int q = lane & 3;
            unsigned rr = __shfl_sync(0xffffffffu, rank, rw);
            if (rr != 0xFFFFFFFFu) {
                float4 v = *reinterpret_cast<const float4*>(ebuf + rw * 64 + q * 16);
                asm volatile("red.global.add.v4.f32 [%0], {%1,%2,%3,%4};"
                             :: "l"(out + (size_t)rr * 16 + q * 4),
                                "f"(v.x), "f"(v.y), "f"(v.z), "f"(v.w)
                             : "memory");
            }
        }
        __syncwarp();
    }
}

// ---------------- launch ----------------
extern "C" void kernel_launch(void* const* d_in, const int* in_sizes, int n_in,
                              void* d_out, int out_size) {
    const float* feats = (const float*)d_in[0];
    const int*   coords = (const int*)d_in[1];
    const float* W = (const float*)d_in[2];
    const float* bias = (const float*)d_in[3];
    float* out = (float*)d_out;
    float* uniqf = out + (size_t)NKTOT * 16;

    cudaFuncSetAttribute(k_gemm, cudaFuncAttributeMaxDynamicSharedMemorySize, SMEM_SZ);

    k_zero<<<ZBLK + 27, 256>>>(W);
    k_mark<<<(NPTS + 255) / 256, 256>>>((const int4*)coords);
    k_scan1<<<NPART, 256>>>();
    k_scan2<<<1, 512>>>();
    k_combo<<<NPART + FOB, 256>>>((float4*)out, (const float4*)bias, uniqf);
    k_rank<<<(NPTS + 255) / 256, 256>>>((const int4*)coords);
    k_gemm<<<NT * KSPL, 256, SMEM_SZ>>>((const float4*)feats, out);
    k_emit<<<(WORDS + 255) / 256, 256>>>(uniqf);
}

// round 9
// speedup vs baseline: 1.2746x; 1.0255x over previous
#include <cuda_runtime.h>
#include <cuda_bf16.h>
#include <cstdint>

#define NPTS   200000
#define CIN    64
#define COUT   16
#define SXD    998
#define SYD    998
#define SZD    38
#define YZ     37924          /* SYD*SZD */
#define SENTV  37848152u
#define NKTOT  5400000        /* NPTS*27 */
#define WORDS  1182755
#define CHUNK  4096
#define NPART  289
#define WPAD   (NPART*CHUNK)
#define ZBLK   (WPAD/1024)
#define FOB    512

#define NOUT   432            /* 27*16 */
#define BSTR   72             /* padded row stride (bf16 elems) = 144B */
#define TILEM  128
#define NT     1563           /* ceil(200000/128) */
#define KSPL   2
#define KB0    14             /* k split: [0,14) and [14,27) */

/* smem layout (bytes) */
#define AH_OFF   0            /* 128*144 = 18432 */
#define AL_OFF   18432
#define BH_OFF   36864        /* 224*144 = 32256 max */
#define BL_OFF   69120
#define SMEM_SZ  101376       /* <112KB -> 2 CTAs/SM */

// ---------------- device scratch ----------------
__device__ __align__(16) unsigned g_bitmap[WPAD];
__device__ __align__(16) unsigned g_coll[WPAD];
__device__ __align__(16) unsigned g_pref[WPAD];
__device__ __align__(16) unsigned g_rank[27 * NPTS];
__device__ __align__(16) unsigned short g_Bh[NOUT * BSTR];
__device__ __align__(16) unsigned short g_Bl[NOUT * BSTR];
__device__ unsigned g_part[NPART];
__device__ unsigned g_M;

static __device__ __forceinline__ uint32_t smem_u32(const void* p) {
    uint32_t a;
    asm("{ .reg .u64 t; cvta.to.shared.u64 t, %1; cvt.u32.u64 %0, t; }" : "=r"(a) : "l"(p));
    return a;
}

#define MMA(C, A, b0v, b1v) \
    asm volatile("mma.sync.aligned.m16n8k16.row.col.f32.bf16.bf16.f32 " \
        "{%0,%1,%2,%3},{%4,%5,%6,%7},{%8,%9},{%0,%1,%2,%3};" \
        : "+f"((C)[0]), "+f"((C)[1]), "+f"((C)[2]), "+f"((C)[3]) \
        : "r"((A)[0]), "r"((A)[1]), "r"((A)[2]), "r"((A)[3]), "r"(b0v), "r"(b1v))

// ---------------- kernels ----------------
// zero both bitmaps + build padded bf16 hi/lo B [og][c]
__global__ void k_zero(const float* __restrict__ W) {
    if (blockIdx.x < 2 * ZBLK) {
        unsigned* dst = (blockIdx.x < ZBLK) ? g_bitmap : g_coll;
        unsigned b = (blockIdx.x < ZBLK) ? blockIdx.x : blockIdx.x - ZBLK;
        unsigned i = b * 1024 + threadIdx.x * 4;
        *reinterpret_cast<uint4*>(&dst[i]) = make_uint4(0u, 0u, 0u, 0u);
    } else {
        int k = blockIdx.x - 2 * ZBLK;
#pragma unroll
        for (int u = 0; u < 4; u++) {
            int idx = threadIdx.x + u * 256;
            int o = idx >> 6, c = idx & 63;
            float v = W[k * 1024 + c * 16 + o];
            __nv_bfloat16 h = __float2bfloat16(v);
            __nv_bfloat16 l = __float2bfloat16(v - __bfloat162float(h));
            int og = k * 16 + o;
            g_Bh[og * BSTR + c] = reinterpret_cast<unsigned short&>(h);
            g_Bl[og * BSTR + c] = reinterpret_cast<unsigned short&>(l);
        }
    }
}

__global__ void k_mark(const int4* __restrict__ coords) {
    int n = blockIdx.x * blockDim.x + threadIdx.x;
    if (n >= NPTS) return;
    int4 c = coords[n];
#pragma unroll
    for (int k = 0; k < 27; k++) {
        int ox = c.y - k / 9;
        int oy = c.z - (k / 3) % 3;
        int oz = c.w - k % 3;
        if ((unsigned)ox < SXD && (unsigned)oy < SYD && (unsigned)oz < SZD) {
            unsigned lin = (unsigned)ox * YZ + (unsigned)oy * SZD + (unsigned)oz;
            unsigned bit = 1u << (lin & 31);
            unsigned old = atomicOr(&g_bitmap[lin >> 5], bit);
            if (old & bit) atomicOr(&g_coll[lin >> 5], bit);
        }
    }
}

__global__ void k_scan1() {
    __shared__ unsigned sh[256];
    unsigned base = blockIdx.x * CHUNK + threadIdx.x * 16;
    unsigned s = 0;
#pragma unroll
    for (int i = 0; i < 16; i += 4) {
        uint4 v = *reinterpret_cast<const uint4*>(&g_bitmap[base + i]);
        s += __popc(v.x) + __popc(v.y) + __popc(v.z) + __popc(v.w);
    }
    sh[threadIdx.x] = s;
    __syncthreads();
    for (int off = 128; off > 0; off >>= 1) {
        if (threadIdx.x < (unsigned)off) sh[threadIdx.x] += sh[threadIdx.x + off];
        __syncthreads();
    }
    if (threadIdx.x == 0) g_part[blockIdx.x] = sh[0];
}

__global__ void k_scan2() {
    __shared__ unsigned sh[512];
    unsigned t = threadIdx.x;
    unsigned v = (t < NPART) ? g_part[t] : 0u;
    sh[t] = v;
    __syncthreads();
    for (int off = 1; off < 512; off <<= 1) {
        unsigned add = (t >= (unsigned)off) ? sh[t - off] : 0u;
        __syncthreads();
        sh[t] += add;
        __syncthreads();
    }
    if (t < NPART) g_part[t] = sh[t] - v;
    if (t == NPART - 1) g_M = sh[t];
}

// combo: blocks [0,NPART): per-word prefix + bias-init of COLLISION rows only;
//        remaining blocks: zero tail rows (j>=M) + SENT-pad uniq tail
__global__ void k_combo(float4* __restrict__ out4, const float4* __restrict__ bias4,
                        float* __restrict__ uniqf) {
    if (blockIdx.x < NPART) {
        float4 bsv[4];
#pragma unroll
        for (int j = 0; j < 4; j++) bsv[j] = __ldg(&bias4[j]);
        __shared__ unsigned sh[256];
        unsigned base = blockIdx.x * CHUNK + threadIdx.x * 16;
        unsigned w[16];
#pragma unroll
        for (int i = 0; i < 16; i += 4)
            *reinterpret_cast<uint4*>(&w[i]) = *reinterpret_cast<const uint4*>(&g_bitmap[base + i]);
        unsigned s = 0;
#pragma unroll
        for (int i = 0; i < 16; i++) s += __popc(w[i]);
        sh[threadIdx.x] = s;
        __syncthreads();
        for (int off = 1; off < 256; off <<= 1) {
            unsigned add = (threadIdx.x >= (unsigned)off) ? sh[threadIdx.x - off] : 0u;
            __syncthreads();
            sh[threadIdx.x] += add;
            __syncthreads();
        }
        unsigned run = g_part[blockIdx.x] + (sh[threadIdx.x] - s);
#pragma unroll 1
        for (int i = 0; i < 16; i++) {
            g_pref[base + i] = run;
            unsigned bits = w[i];
            if (bits) {
                unsigned collw = g_coll[base + i] & bits;
                unsigned r0 = run;
                run += __popc(bits);
                while (collw) {
                    unsigned b = __ffs(collw) - 1u;
                    collw &= collw - 1u;
                    unsigned r = r0 + __popc(bits & ((1u << b) - 1u));
                    float4* o = out4 + (size_t)r * 4;
                    o[0] = bsv[0]; o[1] = bsv[1]; o[2] = bsv[2]; o[3] = bsv[3];
                }
            }
        }
    } else {
        unsigned gt = (blockIdx.x - NPART) * 256u + threadIdx.x;
        unsigned stride = (gridDim.x - NPART) * 256u;
        unsigned M = g_M;
        const float4 z4 = make_float4(0.f, 0.f, 0.f, 0.f);
        for (unsigned i = M * 4u + gt; i < (unsigned)NKTOT * 4u; i += stride)
            out4[i] = z4;
        for (unsigned j = M + gt; j < (unsigned)NKTOT; j += stride)
            uniqf[j] = 37848152.0f;
    }
}

// precompute rank[k][n] (0xFFFFFFFF = invalid; bit31 = collision)
__global__ void k_rank(const int4* __restrict__ coords) {
    int n = blockIdx.x * blockDim.x + threadIdx.x;
    if (n >= NPTS) return;
    int4 c = coords[n];
#pragma unroll
    for (int k = 0; k < 27; k++) {
        int ox = c.y - k / 9;
        int oy = c.z - (k / 3) % 3;
        int oz = c.w - k % 3;
        unsigned rank = 0xFFFFFFFFu;
        if ((unsigned)ox < SXD && (unsigned)oy < SYD && (unsigned)oz < SZD) {
            unsigned lin = (unsigned)ox * YZ + (unsigned)oy * SZD + (unsigned)oz;
            unsigned word = lin >> 5;
            unsigned bpos = lin & 31;
            rank = __ldg(&g_pref[word]) +
                   __popc(__ldg(&g_bitmap[word]) & ((1u << bpos) - 1u));
            if ((__ldg(&g_coll[word]) >> bpos) & 1u) rank |= 0x80000000u;
        }
        g_rank[k * NPTS + n] = rank;
    }
}

__global__ void k_emit(float* __restrict__ uniqf) {
    unsigned i = blockIdx.x * blockDim.x + threadIdx.x;
    if (i >= WORDS) return;
    unsigned bits = g_bitmap[i];
    if (!bits) return;
    unsigned r = g_pref[i];
    unsigned vbase = i << 5;
    while (bits) {
        unsigned b = __ffs(bits) - 1u;
        bits &= bits - 1u;
        uniqf[r++] = (float)(vbase + b);
    }
}

// ---------------- HMMA GEMM + collision-split scatter (k-split, 2 CTA/SM) ----
__global__ void __launch_bounds__(256, 2) k_gemm(
    const float4* __restrict__ feats4, float* __restrict__ out,
    const float4* __restrict__ bias4)
{
    extern __shared__ char smem[];
    uint32_t sb = smem_u32(smem);
    int tid = threadIdx.x;
    int wid = tid >> 5;
    int lane = tid & 31;
    int tile = blockIdx.x >> 1;
    int khalf = blockIdx.x & 1;
    int kbeg = khalf ? KB0 : 0;
    int kend = khalf ? 27 : KB0;
    int base_n = tile * TILEM;

    // stage B hi/lo for our k-range
    {
        int nu4 = (kend - kbeg) * 144;
        const uint4* bh = reinterpret_cast<const uint4*>(g_Bh) + kbeg * 144;
        const uint4* bl = reinterpret_cast<const uint4*>(g_Bl) + kbeg * 144;
        uint4* dh = reinterpret_cast<uint4*>(smem + BH_OFF);
        uint4* dl = reinterpret_cast<uint4*>(smem + BL_OFF);
        for (int i = tid; i < nu4; i += 256) {
            dh[i] = __ldg(&bh[i]);
            dl[i] = __ldg(&bl[i]);
        }
    }
    // stage A tile (128 rows) as bf16 hi/lo
    for (int i = tid; i < 2048; i += 256) {
        int r = i >> 4, col = i & 15;
        int n = base_n + r;
        float4 f = (n < NPTS) ? __ldg(&feats4[(size_t)n * 16 + col])
                              : make_float4(0.f, 0.f, 0.f, 0.f);
        __nv_bfloat16 h0 = __float2bfloat16(f.x), h1 = __float2bfloat16(f.y);
        __nv_bfloat16 h2 = __float2bfloat16(f.z), h3 = __float2bfloat16(f.w);
        __nv_bfloat16 l0 = __float2bfloat16(f.x - __bfloat162float(h0));
        __nv_bfloat16 l1 = __float2bfloat16(f.y - __bfloat162float(h1));
        __nv_bfloat16 l2 = __float2bfloat16(f.z - __bfloat162float(h2));
        __nv_bfloat16 l3 = __float2bfloat16(f.w - __bfloat162float(h3));
        uint2 hv, lv;
        hv.x = (unsigned)reinterpret_cast<unsigned short&>(h0) |
               ((unsigned)reinterpret_cast<unsigned short&>(h1) << 16);
        hv.y = (unsigned)reinterpret_cast<unsigned short&>(h2) |
               ((unsigned)reinterpret_cast<unsigned short&>(h3) << 16);
        lv.x = (unsigned)reinterpret_cast<unsigned short&>(l0) |
               ((unsigned)reinterpret_cast<unsigned short&>(l1) << 16);
        lv.y = (unsigned)reinterpret_cast<unsigned short&>(l2) |
               ((unsigned)reinterpret_cast<unsigned short&>(l3) << 16);
        unsigned off = (unsigned)r * 144u + (unsigned)col * 8u;
        *reinterpret_cast<uint2*>(smem + AH_OFF + off) = hv;
        *reinterpret_cast<uint2*>(smem + AL_OFF + off) = lv;
    }
    __syncthreads();

    // per-warp A fragments (16 rows)
    uint32_t ah[4][4], al[4][4];
    {
        uint32_t abase = sb + AH_OFF + (unsigned)(wid * 16 + (lane & 15)) * 144u
                       + ((unsigned)(lane >> 4) & 1u) * 16u;
#pragma unroll
        for (int kk = 0; kk < 4; kk++) {
            uint32_t a0 = abase + kk * 32u;
            asm volatile("ldmatrix.sync.aligned.m8n8.x4.shared.b16 {%0,%1,%2,%3},[%4];"
                : "=r"(ah[kk][0]), "=r"(ah[kk][1]), "=r"(ah[kk][2]), "=r"(ah[kk][3]) : "r"(a0));
            uint32_t a1 = a0 + (AL_OFF - AH_OFF);
            asm volatile("ldmatrix.sync.aligned.m8n8.x4.shared.b16 {%0,%1,%2,%3},[%4];"
                : "=r"(al[kk][0]), "=r"(al[kk][1]), "=r"(al[kk][2]), "=r"(al[kk][3]) : "r"(a1));
        }
    }
    __syncthreads();                            // A smem now free -> reuse as ebuf

    char* ebuf = smem + wid * 1024;             // 16 rows x 64B
    uint32_t bl_lane = (unsigned)(lane & 7) * 144u + ((unsigned)(lane >> 3) & 1u) * 16u;
    float4 bq = __ldg(&bias4[lane & 3]);        // bias quarter for this lane's q

#pragma unroll 1
    for (int k = kbeg; k < kend; k++) {
        // coalesced rank load (lanes 0..15 hold rows) — GUARDED against n >= NPTS
        unsigned rank = 0xFFFFFFFFu;
        int rown = base_n + wid * 16 + lane;
        if (lane < 16 && rown < NPTS)
            rank = __ldg(&g_rank[(size_t)k * NPTS + rown]);

        // B fragments for this k (hi + lo), loaded once
        uint32_t bh[4][2][2], blo[4][2][2];
        uint32_t bk = sb + (unsigned)(k - kbeg) * 2304u + bl_lane;
#pragma unroll
        for (int kk = 0; kk < 4; kk++) {
#pragma unroll
            for (int n2 = 0; n2 < 2; n2++) {
                uint32_t ba = bk + (unsigned)(n2 * 8) * 144u + (unsigned)kk * 32u;
                asm volatile("ldmatrix.sync.aligned.m8n8.x2.shared.b16 {%0,%1},[%2];"
                             : "=r"(bh[kk][n2][0]), "=r"(bh[kk][n2][1])
                             : "r"(ba + BH_OFF));
                asm volatile("ldmatrix.sync.aligned.m8n8.x2.shared.b16 {%0,%1},[%2];"
                             : "=r"(blo[kk][n2][0]), "=r"(blo[kk][n2][1])
                             : "r"(ba + BL_OFF));
            }
        }

        float c[2][4];
#pragma unroll
        for (int n2 = 0; n2 < 2; n2++)
#pragma unroll
            for (int q = 0; q < 4; q++) c[n2][q] = 0.f;

#pragma unroll
        for (int kk = 0; kk < 4; kk++) {
#pragma unroll
            for (int n2 = 0; n2 < 2; n2++) {
                MMA(c[n2], ah[kk], bh[kk][n2][0], bh[kk][n2][1]);
                MMA(c[n2], al[kk], bh[kk][n2][0], bh[kk][n2][1]);
                MMA(c[n2], ah[kk], blo[kk][n2][0], blo[kk][n2][1]);
            }
        }

        __syncwarp();
        {
            int r0 = lane >> 2;
            int cb = (lane & 3) * 2;
#pragma unroll
            for (int n2 = 0; n2 < 2; n2++) {
                int colb = n2 * 8 + cb;
                *reinterpret_cast<float2*>(ebuf + r0 * 64 + colb * 4) =
                    make_float2(c[n2][0], c[n2][1]);
                *reinterpret_cast<float2*>(ebuf + (r0 + 8) * 64 + colb * 4) =
                    make_float2(c[n2][2], c[n2][3]);
            }
        }
        __syncwarp();
#pragma unroll
        for (int j = 0; j < 2; j++) {
            int rw = j * 8 + (lane >> 2);
            int q = lane & 3;
            unsigned rr = __shfl_sync(0xffffffffu, rank, rw);
            if (rr != 0xFFFFFFFFu) {
                float4 v = *reinterpret_cast<const float4*>(ebuf + rw * 64 + q * 16);
                if (rr & 0x80000000u) {
                    asm volatile("red.global.add.v4.f32 [%0], {%1,%2,%3,%4};"
                                 :: "l"(out + (size_t)(rr & 0x7FFFFFFFu) * 16 + q * 4),
                                    "f"(v.x), "f"(v.y), "f"(v.z), "f"(v.w)
                                 : "memory");
                } else {
                    float4 w = make_float4(v.x + bq.x, v.y + bq.y,
                                           v.z + bq.z, v.w + bq.w);
                    *reinterpret_cast<float4*>(out + (size_t)rr * 16 + q * 4) = w;
                }
            }
        }
        __syncwarp();
    }
}

// ---------------- launch ----------------
extern "C" void kernel_launch(void* const* d_in, const int* in_sizes, int n_in,
                              void* d_out, int out_size) {
    const float* feats = (const float*)d_in[0];
    const int*   coords = (const int*)d_in[1];
    const float* W = (const float*)d_in[2];
    const float* bias = (const float*)d_in[3];
    float* out = (float*)d_out;
    float* uniqf = out + (size_t)NKTOT * 16;

    cudaFuncSetAttribute(k_gemm, cudaFuncAttributeMaxDynamicSharedMemorySize, SMEM_SZ);

    k_zero<<<2 * ZBLK + 27, 256>>>(W);
    k_mark<<<(NPTS + 255) / 256, 256>>>((const int4*)coords);
    k_scan1<<<NPART, 256>>>();
    k_scan2<<<1, 512>>>();
    k_combo<<<NPART + FOB, 256>>>((float4*)out, (const float4*)bias, uniqf);
    k_rank<<<(NPTS + 255) / 256, 256>>>((const int4*)coords);
    k_gemm<<<NT * KSPL, 256, SMEM_SZ>>>((const float4*)feats, out, (const float4*)bias);
    k_emit<<<(WORDS + 255) / 256, 256>>>(uniqf);
}

// round 10
// speedup vs baseline: 1.4770x; 1.1588x over previous
#include <cuda_runtime.h>
#include <cuda_fp16.h>
#include <cstdint>

#define NPTS   200000
#define CIN    64
#define COUT   16
#define SXD    998
#define SYD    998
#define SZD    38
#define YZ     37924          /* SYD*SZD */
#define SENTV  37848152u
#define NKTOT  5400000        /* NPTS*27 */
#define WORDS  1182755
#define CHUNK  4096
#define NPART  289
#define WPAD   (NPART*CHUNK)
#define ZBLK   (WPAD/1024)
#define FOB    512

#define NOUT   432            /* 27*16 */
#define BSTR   72             /* padded row stride (fp16 elems) = 144B */
#define TILEM  128
#define NT     1563           /* ceil(200000/128) */
#define KSPL   2
#define KB0    14             /* k split: [0,14) and [14,27) */

/* smem layout (bytes) */
#define AH_OFF   0            /* 128*144 = 18432 */
#define AL_OFF   18432
#define BH_OFF   36864        /* 224*144 = 32256 max */
#define SMEM_SZ  69120        /* 3 CTAs/SM */

// ---------------- device scratch ----------------
__device__ __align__(16) unsigned g_bitmap[WPAD];
__device__ __align__(16) unsigned g_coll[WPAD];
__device__ __align__(16) unsigned g_pref[WPAD];
__device__ __align__(16) unsigned g_rank[27 * NPTS];
__device__ __align__(16) unsigned short g_Bh[NOUT * BSTR];
__device__ unsigned g_part[NPART];
__device__ unsigned g_M;

static __device__ __forceinline__ uint32_t smem_u32(const void* p) {
    uint32_t a;
    asm("{ .reg .u64 t; cvta.to.shared.u64 t, %1; cvt.u32.u64 %0, t; }" : "=r"(a) : "l"(p));
    return a;
}

#define MMA(C, A, b0v, b1v) \
    asm volatile("mma.sync.aligned.m16n8k16.row.col.f32.f16.f16.f32 " \
        "{%0,%1,%2,%3},{%4,%5,%6,%7},{%8,%9},{%0,%1,%2,%3};" \
        : "+f"((C)[0]), "+f"((C)[1]), "+f"((C)[2]), "+f"((C)[3]) \
        : "r"((A)[0]), "r"((A)[1]), "r"((A)[2]), "r"((A)[3]), "r"(b0v), "r"(b1v))

// ---------------- kernels ----------------
// zero both bitmaps + build padded fp16 B [og][c]
__global__ void k_zero(const float* __restrict__ W) {
    if (blockIdx.x < 2 * ZBLK) {
        unsigned* dst = (blockIdx.x < ZBLK) ? g_bitmap : g_coll;
        unsigned b = (blockIdx.x < ZBLK) ? blockIdx.x : blockIdx.x - ZBLK;
        unsigned i = b * 1024 + threadIdx.x * 4;
        *reinterpret_cast<uint4*>(&dst[i]) = make_uint4(0u, 0u, 0u, 0u);
    } else {
        int k = blockIdx.x - 2 * ZBLK;
#pragma unroll
        for (int u = 0; u < 4; u++) {
            int idx = threadIdx.x + u * 256;
            int o = idx >> 6, c = idx & 63;
            float v = W[k * 1024 + c * 16 + o];
            __half h = __float2half_rn(v);
            int og = k * 16 + o;
            g_Bh[og * BSTR + c] = reinterpret_cast<unsigned short&>(h);
        }
    }
}

__global__ void k_mark(const int4* __restrict__ coords) {
    int n = blockIdx.x * blockDim.x + threadIdx.x;
    if (n >= NPTS) return;
    int4 c = coords[n];
#pragma unroll
    for (int k = 0; k < 27; k++) {
        int ox = c.y - k / 9;
        int oy = c.z - (k / 3) % 3;
        int oz = c.w - k % 3;
        if ((unsigned)ox < SXD && (unsigned)oy < SYD && (unsigned)oz < SZD) {
            unsigned lin = (unsigned)ox * YZ + (unsigned)oy * SZD + (unsigned)oz;
            unsigned bit = 1u << (lin & 31);
            unsigned old = atomicOr(&g_bitmap[lin >> 5], bit);
            if (old & bit) atomicOr(&g_coll[lin >> 5], bit);
        }
    }
}

__global__ void k_scan1() {
    __shared__ unsigned sh[256];
    unsigned base = blockIdx.x * CHUNK + threadIdx.x * 16;
    unsigned s = 0;
#pragma unroll
    for (int i = 0; i < 16; i += 4) {
        uint4 v = *reinterpret_cast<const uint4*>(&g_bitmap[base + i]);
        s += __popc(v.x) + __popc(v.y) + __popc(v.z) + __popc(v.w);
    }
    sh[threadIdx.x] = s;
    __syncthreads();
    for (int off = 128; off > 0; off >>= 1) {
        if (threadIdx.x < (unsigned)off) sh[threadIdx.x] += sh[threadIdx.x + off];
        __syncthreads();
    }
    if (threadIdx.x == 0) g_part[blockIdx.x] = sh[0];
}

__global__ void k_scan2() {
    __shared__ unsigned sh[512];
    unsigned t = threadIdx.x;
    unsigned v = (t < NPART) ? g_part[t] : 0u;
    sh[t] = v;
    __syncthreads();
    for (int off = 1; off < 512; off <<= 1) {
        unsigned add = (t >= (unsigned)off) ? sh[t - off] : 0u;
        __syncthreads();
        sh[t] += add;
        __syncthreads();
    }
    if (t < NPART) g_part[t] = sh[t] - v;
    if (t == NPART - 1) g_M = sh[t];
}

// combo: blocks [0,NPART): per-word prefix + bias-init of COLLISION rows only;
//        remaining blocks: zero tail rows (j>=M) + SENT-pad uniq tail
__global__ void k_combo(float4* __restrict__ out4, const float4* __restrict__ bias4,
                        float* __restrict__ uniqf) {
    if (blockIdx.x < NPART) {
        float4 bsv[4];
#pragma unroll
        for (int j = 0; j < 4; j++) bsv[j] = __ldg(&bias4[j]);
        __shared__ unsigned sh[256];
        unsigned base = blockIdx.x * CHUNK + threadIdx.x * 16;
        unsigned w[16];
#pragma unroll
        for (int i = 0; i < 16; i += 4)
            *reinterpret_cast<uint4*>(&w[i]) = *reinterpret_cast<const uint4*>(&g_bitmap[base + i]);
        unsigned s = 0;
#pragma unroll
        for (int i = 0; i < 16; i++) s += __popc(w[i]);
        sh[threadIdx.x] = s;
        __syncthreads();
        for (int off = 1; off < 256; off <<= 1) {
            unsigned add = (threadIdx.x >= (unsigned)off) ? sh[threadIdx.x - off] : 0u;
            __syncthreads();
            sh[threadIdx.x] += add;
            __syncthreads();
        }
        unsigned run = g_part[blockIdx.x] + (sh[threadIdx.x] - s);
#pragma unroll 1
        for (int i = 0; i < 16; i++) {
            g_pref[base + i] = run;
            unsigned bits = w[i];
            if (bits) {
                unsigned collw = g_coll[base + i] & bits;
                unsigned r0 = run;
                run += __popc(bits);
                while (collw) {
                    unsigned b = __ffs(collw) - 1u;
                    collw &= collw - 1u;
                    unsigned r = r0 + __popc(bits & ((1u << b) - 1u));
                    float4* o = out4 + (size_t)r * 4;
                    o[0] = bsv[0]; o[1] = bsv[1]; o[2] = bsv[2]; o[3] = bsv[3];
                }
            }
        }
    } else {
        unsigned gt = (blockIdx.x - NPART) * 256u + threadIdx.x;
        unsigned stride = (gridDim.x - NPART) * 256u;
        unsigned M = g_M;
        const float4 z4 = make_float4(0.f, 0.f, 0.f, 0.f);
        for (unsigned i = M * 4u + gt; i < (unsigned)NKTOT * 4u; i += stride)
            out4[i] = z4;
        for (unsigned j = M + gt; j < (unsigned)NKTOT; j += stride)
            uniqf[j] = 37848152.0f;
    }
}

// precompute rank[k][n] (0xFFFFFFFF = invalid; bit31 = collision)
__global__ void k_rank(const int4* __restrict__ coords) {
    int n = blockIdx.x * blockDim.x + threadIdx.x;
    if (n >= NPTS) return;
    int4 c = coords[n];
#pragma unroll
    for (int k = 0; k < 27; k++) {
        int ox = c.y - k / 9;
        int oy = c.z - (k / 3) % 3;
        int oz = c.w - k % 3;
        unsigned rank = 0xFFFFFFFFu;
        if ((unsigned)ox < SXD && (unsigned)oy < SYD && (unsigned)oz < SZD) {
            unsigned lin = (unsigned)ox * YZ + (unsigned)oy * SZD + (unsigned)oz;
            unsigned word = lin >> 5;
            unsigned bpos = lin & 31;
            rank = __ldg(&g_pref[word]) +
                   __popc(__ldg(&g_bitmap[word]) & ((1u << bpos) - 1u));
            if ((__ldg(&g_coll[word]) >> bpos) & 1u) rank |= 0x80000000u;
        }
        g_rank[k * NPTS + n] = rank;
    }
}

__global__ void k_emit(float* __restrict__ uniqf) {
    unsigned i = blockIdx.x * blockDim.x + threadIdx.x;
    if (i >= WORDS) return;
    unsigned bits = g_bitmap[i];
    if (!bits) return;
    unsigned r = g_pref[i];
    unsigned vbase = i << 5;
    while (bits) {
        unsigned b = __ffs(bits) - 1u;
        bits &= bits - 1u;
        uniqf[r++] = (float)(vbase + b);
    }
}

// ------- fp16 split HMMA GEMM + collision-split scatter (k-split, 3 CTA/SM) ----
__global__ void __launch_bounds__(256, 3) k_gemm(
    const float4* __restrict__ feats4, float* __restrict__ out,
    const float4* __restrict__ bias4)
{
    extern __shared__ char smem[];
    uint32_t sb = smem_u32(smem);
    int tid = threadIdx.x;
    int wid = tid >> 5;
    int lane = tid & 31;
    int tile = blockIdx.x >> 1;
    int khalf = blockIdx.x & 1;
    int kbeg = khalf ? KB0 : 0;
    int kend = khalf ? 27 : KB0;
    int base_n = tile * TILEM;

    // stage B (fp16) for our k-range
    {
        int nu4 = (kend - kbeg) * 144;
        const uint4* bh = reinterpret_cast<const uint4*>(g_Bh) + kbeg * 144;
        uint4* dh = reinterpret_cast<uint4*>(smem + BH_OFF);
        for (int i = tid; i < nu4; i += 256)
            dh[i] = __ldg(&bh[i]);
    }
    // stage A tile (128 rows) as fp16 hi/lo
    for (int i = tid; i < 2048; i += 256) {
        int r = i >> 4, col = i & 15;
        int n = base_n + r;
        float4 f = (n < NPTS) ? __ldg(&feats4[(size_t)n * 16 + col])
                              : make_float4(0.f, 0.f, 0.f, 0.f);
        __half h0 = __float2half_rn(f.x), h1 = __float2half_rn(f.y);
        __half h2 = __float2half_rn(f.z), h3 = __float2half_rn(f.w);
        __half l0 = __float2half_rn(f.x - __half2float(h0));
        __half l1 = __float2half_rn(f.y - __half2float(h1));
        __half l2 = __float2half_rn(f.z - __half2float(h2));
        __half l3 = __float2half_rn(f.w - __half2float(h3));
        uint2 hv, lv;
        hv.x = (unsigned)reinterpret_cast<unsigned short&>(h0) |
               ((unsigned)reinterpret_cast<unsigned short&>(h1) << 16);
        hv.y = (unsigned)reinterpret_cast<unsigned short&>(h2) |
               ((unsigned)reinterpret_cast<unsigned short&>(h3) << 16);
        lv.x = (unsigned)reinterpret_cast<unsigned short&>(l0) |
               ((unsigned)reinterpret_cast<unsigned short&>(l1) << 16);
        lv.y = (unsigned)reinterpret_cast<unsigned short&>(l2) |
               ((unsigned)reinterpret_cast<unsigned short&>(l3) << 16);
        unsigned off = (unsigned)r * 144u + (unsigned)col * 8u;
        *reinterpret_cast<uint2*>(smem + AH_OFF + off) = hv;
        *reinterpret_cast<uint2*>(smem + AL_OFF + off) = lv;
    }
    __syncthreads();

    // per-warp A fragments (16 rows)
    uint32_t ah[4][4], al[4][4];
    {
        uint32_t abase = sb + AH_OFF + (unsigned)(wid * 16 + (lane & 15)) * 144u
                       + ((unsigned)(lane >> 4) & 1u) * 16u;
#pragma unroll
        for (int kk = 0; kk < 4; kk++) {
            uint32_t a0 = abase + kk * 32u;
            asm volatile("ldmatrix.sync.aligned.m8n8.x4.shared.b16 {%0,%1,%2,%3},[%4];"
                : "=r"(ah[kk][0]), "=r"(ah[kk][1]), "=r"(ah[kk][2]), "=r"(ah[kk][3]) : "r"(a0));
            uint32_t a1 = a0 + (AL_OFF - AH_OFF);
            asm volatile("ldmatrix.sync.aligned.m8n8.x4.shared.b16 {%0,%1,%2,%3},[%4];"
                : "=r"(al[kk][0]), "=r"(al[kk][1]), "=r"(al[kk][2]), "=r"(al[kk][3]) : "r"(a1));
        }
    }
    __syncthreads();                            // A smem now free -> reuse as ebuf

    char* ebuf = smem + wid * 1024;             // 16 rows x 64B
    uint32_t bl_lane = (unsigned)(lane & 7) * 144u + ((unsigned)(lane >> 3) & 1u) * 16u;
    float4 bq = __ldg(&bias4[lane & 3]);        // bias quarter for this lane's q

#pragma unroll 1
    for (int k = kbeg; k < kend; k++) {
        // coalesced rank load (lanes 0..15 hold rows) — guarded
        unsigned rank = 0xFFFFFFFFu;
        int rown = base_n + wid * 16 + lane;
        if (lane < 16 && rown < NPTS)
            rank = __ldg(&g_rank[(size_t)k * NPTS + rown]);

        // B fragments for this k, loaded once
        uint32_t bh[4][2][2];
        uint32_t bk = sb + BH_OFF + (unsigned)(k - kbeg) * 2304u + bl_lane;
#pragma unroll
        for (int kk = 0; kk < 4; kk++) {
#pragma unroll
            for (int n2 = 0; n2 < 2; n2++) {
                uint32_t ba = bk + (unsigned)(n2 * 8) * 144u + (unsigned)kk * 32u;
                asm volatile("ldmatrix.sync.aligned.m8n8.x2.shared.b16 {%0,%1},[%2];"
                             : "=r"(bh[kk][n2][0]), "=r"(bh[kk][n2][1])
                             : "r"(ba));
            }
        }

        float c[2][4];
#pragma unroll
        for (int n2 = 0; n2 < 2; n2++)
#pragma unroll
            for (int q = 0; q < 4; q++) c[n2][q] = 0.f;

#pragma unroll
        for (int kk = 0; kk < 4; kk++) {
#pragma unroll
            for (int n2 = 0; n2 < 2; n2++) {
                MMA(c[n2], ah[kk], bh[kk][n2][0], bh[kk][n2][1]);
                MMA(c[n2], al[kk], bh[kk][n2][0], bh[kk][n2][1]);
            }
        }

        __syncwarp();
        {
            int r0 = lane >> 2;
            int cb = (lane & 3) * 2;
#pragma unroll
            for (int n2 = 0; n2 < 2; n2++) {
                int colb = n2 * 8 + cb;
                *reinterpret_cast<float2*>(ebuf + r0 * 64 + colb * 4) =
                    make_float2(c[n2][0], c[n2][1]);
                *reinterpret_cast<float2*>(ebuf + (r0 + 8) * 64 + colb * 4) =
                    make_float2(c[n2][2], c[n2][3]);
            }
        }
        __syncwarp();
#pragma unroll
        for (int j = 0; j < 2; j++) {
            int rw = j * 8 + (lane >> 2);
            int q = lane & 3;
            unsigned rr = __shfl_sync(0xffffffffu, rank, rw);
            if (rr != 0xFFFFFFFFu) {
                float4 v = *reinterpret_cast<const float4*>(ebuf + rw * 64 + q * 16);
                if (rr & 0x80000000u) {
                    asm volatile("red.global.add.v4.f32 [%0], {%1,%2,%3,%4};"
                                 :: "l"(out + (size_t)(rr & 0x7FFFFFFFu) * 16 + q * 4),
                                    "f"(v.x), "f"(v.y), "f"(v.z), "f"(v.w)
                                 : "memory");
                } else {
                    float4 w = make_float4(v.x + bq.x, v.y + bq.y,
                                           v.z + bq.z, v.w + bq.w);
                    *reinterpret_cast<float4*>(out + (size_t)rr * 16 + q * 4) = w;
                }
            }
        }
        __syncwarp();
    }
}

// ---------------- launch ----------------
extern "C" void kernel_launch(void* const* d_in, const int* in_sizes, int n_in,
                              void* d_out, int out_size) {
    const float* feats = (const float*)d_in[0];
    const int*   coords = (const int*)d_in[1];
    const float* W = (const float*)d_in[2];
    const float* bias = (const float*)d_in[3];
    float* out = (float*)d_out;
    float* uniqf = out + (size_t)NKTOT * 16;

    cudaFuncSetAttribute(k_gemm, cudaFuncAttributeMaxDynamicSharedMemorySize, SMEM_SZ);

    k_zero<<<2 * ZBLK + 27, 256>>>(W);
    k_mark<<<(NPTS + 255) / 256, 256>>>((const int4*)coords);
    k_scan1<<<NPART, 256>>>();
    k_scan2<<<1, 512>>>();
    k_combo<<<NPART + FOB, 256>>>((float4*)out, (const float4*)bias, uniqf);
    k_rank<<<(NPTS + 255) / 256, 256>>>((const int4*)coords);
    k_gemm<<<NT * KSPL, 256, SMEM_SZ>>>((const float4*)feats, out, (const float4*)bias);
    k_emit<<<(WORDS + 255) / 256, 256>>>(uniqf);
}

// round 11
// speedup vs baseline: 1.5074x; 1.0206x over previous
#include <cuda_runtime.h>
#include <cuda_fp16.h>
#include <cstdint>

#define NPTS   200000
#define CIN    64
#define COUT   16
#define SXD    998
#define SYD    998
#define SZD    38
#define YZ     37924          /* SYD*SZD */
#define SENTV  37848152u
#define NKTOT  5400000        /* NPTS*27 */
#define WORDS  1182755
#define CHUNK  4096
#define NPART  289
#define WPAD   (NPART*CHUNK)
#define ZBLK   (WPAD/1024)
#define FOB    512

#define NOUT   432            /* 27*16 */
#define BSTR   72             /* padded row stride (fp16 elems) = 144B */
#define TILEM  128
#define NT     1563           /* ceil(200000/128) */
#define KB0    14             /* k split: [0,14) and [14,27) */
#define NSTREAM 222           /* tile streams; grid = 2*NSTREAM = 444 = 3/SM */

/* smem layout (bytes) */
#define AH_OFF   0            /* 128*144 = 18432 */
#define AL_OFF   18432
#define BH_OFF   36864        /* 224*144 = 32256 max */
#define SMEM_SZ  69120        /* 3 CTAs/SM */

// ---------------- device scratch ----------------
__device__ __align__(16) unsigned g_bitmap[WPAD];
__device__ __align__(16) unsigned g_coll[WPAD];
__device__ __align__(16) unsigned g_pref[WPAD];
__device__ __align__(16) unsigned g_rank[27 * NPTS];
__device__ __align__(16) unsigned short g_Bh[NOUT * BSTR];
__device__ unsigned g_part[NPART];
__device__ unsigned g_M;

static __device__ __forceinline__ uint32_t smem_u32(const void* p) {
    uint32_t a;
    asm("{ .reg .u64 t; cvta.to.shared.u64 t, %1; cvt.u32.u64 %0, t; }" : "=r"(a) : "l"(p));
    return a;
}

#define MMA(C, A, b0v, b1v) \
    asm volatile("mma.sync.aligned.m16n8k16.row.col.f32.f16.f16.f32 " \
        "{%0,%1,%2,%3},{%4,%5,%6,%7},{%8,%9},{%0,%1,%2,%3};" \
        : "+f"((C)[0]), "+f"((C)[1]), "+f"((C)[2]), "+f"((C)[3]) \
        : "r"((A)[0]), "r"((A)[1]), "r"((A)[2]), "r"((A)[3]), "r"(b0v), "r"(b1v))

// ---------------- kernels ----------------
// zero both bitmaps + build padded fp16 B [og][c]
__global__ void k_zero(const float* __restrict__ W) {
    if (blockIdx.x < 2 * ZBLK) {
        unsigned* dst = (blockIdx.x < ZBLK) ? g_bitmap : g_coll;
        unsigned b = (blockIdx.x < ZBLK) ? blockIdx.x : blockIdx.x - ZBLK;
        unsigned i = b * 1024 + threadIdx.x * 4;
        *reinterpret_cast<uint4*>(&dst[i]) = make_uint4(0u, 0u, 0u, 0u);
    } else {
        int k = blockIdx.x - 2 * ZBLK;
#pragma unroll
        for (int u = 0; u < 4; u++) {
            int idx = threadIdx.x + u * 256;
            int o = idx >> 6, c = idx & 63;
            float v = W[k * 1024 + c * 16 + o];
            __half h = __float2half_rn(v);
            int og = k * 16 + o;
            g_Bh[og * BSTR + c] = reinterpret_cast<unsigned short&>(h);
        }
    }
}

__global__ void k_mark(const int4* __restrict__ coords) {
    int n = blockIdx.x * blockDim.x + threadIdx.x;
    if (n >= NPTS) return;
    int4 c = coords[n];
#pragma unroll
    for (int k = 0; k < 27; k++) {
        int ox = c.y - k / 9;
        int oy = c.z - (k / 3) % 3;
        int oz = c.w - k % 3;
        if ((unsigned)ox < SXD && (unsigned)oy < SYD && (unsigned)oz < SZD) {
            unsigned lin = (unsigned)ox * YZ + (unsigned)oy * SZD + (unsigned)oz;
            unsigned bit = 1u << (lin & 31);
            unsigned old = atomicOr(&g_bitmap[lin >> 5], bit);
            if (old & bit) atomicOr(&g_coll[lin >> 5], bit);
        }
    }
}

__global__ void k_scan1() {
    __shared__ unsigned sh[256];
    unsigned base = blockIdx.x * CHUNK + threadIdx.x * 16;
    unsigned s = 0;
#pragma unroll
    for (int i = 0; i < 16; i += 4) {
        uint4 v = *reinterpret_cast<const uint4*>(&g_bitmap[base + i]);
        s += __popc(v.x) + __popc(v.y) + __popc(v.z) + __popc(v.w);
    }
    sh[threadIdx.x] = s;
    __syncthreads();
    for (int off = 128; off > 0; off >>= 1) {
        if (threadIdx.x < (unsigned)off) sh[threadIdx.x] += sh[threadIdx.x + off];
        __syncthreads();
    }
    if (threadIdx.x == 0) g_part[blockIdx.x] = sh[0];
}

__global__ void k_scan2() {
    __shared__ unsigned sh[512];
    unsigned t = threadIdx.x;
    unsigned v = (t < NPART) ? g_part[t] : 0u;
    sh[t] = v;
    __syncthreads();
    for (int off = 1; off < 512; off <<= 1) {
        unsigned add = (t >= (unsigned)off) ? sh[t - off] : 0u;
        __syncthreads();
        sh[t] += add;
        __syncthreads();
    }
    if (t < NPART) g_part[t] = sh[t] - v;
    if (t == NPART - 1) g_M = sh[t];
}

// combo: blocks [0,NPART): per-word prefix + bias-init of COLLISION rows only;
//        remaining blocks: zero tail rows (j>=M) + SENT-pad uniq tail
__global__ void k_combo(float4* __restrict__ out4, const float4* __restrict__ bias4,
                        float* __restrict__ uniqf) {
    if (blockIdx.x < NPART) {
        float4 bsv[4];
#pragma unroll
        for (int j = 0; j < 4; j++) bsv[j] = __ldg(&bias4[j]);
        __shared__ unsigned sh[256];
        unsigned base = blockIdx.x * CHUNK + threadIdx.x * 16;
        unsigned w[16];
#pragma unroll
        for (int i = 0; i < 16; i += 4)
            *reinterpret_cast<uint4*>(&w[i]) = *reinterpret_cast<const uint4*>(&g_bitmap[base + i]);
        unsigned s = 0;
#pragma unroll
        for (int i = 0; i < 16; i++) s += __popc(w[i]);
        sh[threadIdx.x] = s;
        __syncthreads();
        for (int off = 1; off < 256; off <<= 1) {
            unsigned add = (threadIdx.x >= (unsigned)off) ? sh[threadIdx.x - off] : 0u;
            __syncthreads();
            sh[threadIdx.x] += add;
            __syncthreads();
        }
        unsigned run = g_part[blockIdx.x] + (sh[threadIdx.x] - s);
#pragma unroll 1
        for (int i = 0; i < 16; i++) {
            g_pref[base + i] = run;
            unsigned bits = w[i];
            if (bits) {
                unsigned collw = g_coll[base + i] & bits;
                unsigned r0 = run;
                run += __popc(bits);
                while (collw) {
                    unsigned b = __ffs(collw) - 1u;
                    collw &= collw - 1u;
                    unsigned r = r0 + __popc(bits & ((1u << b) - 1u));
                    float4* o = out4 + (size_t)r * 4;
                    o[0] = bsv[0]; o[1] = bsv[1]; o[2] = bsv[2]; o[3] = bsv[3];
                }
            }
        }
    } else {
        unsigned gt = (blockIdx.x - NPART) * 256u + threadIdx.x;
        unsigned stride = (gridDim.x - NPART) * 256u;
        unsigned M = g_M;
        const float4 z4 = make_float4(0.f, 0.f, 0.f, 0.f);
        for (unsigned i = M * 4u + gt; i < (unsigned)NKTOT * 4u; i += stride)
            out4[i] = z4;
        for (unsigned j = M + gt; j < (unsigned)NKTOT; j += stride)
            uniqf[j] = 37848152.0f;
    }
}

// precompute rank[k][n] (0xFFFFFFFF = invalid; bit31 = collision)
__global__ void k_rank(const int4* __restrict__ coords) {
    int n = blockIdx.x * blockDim.x + threadIdx.x;
    if (n >= NPTS) return;
    int4 c = coords[n];
#pragma unroll
    for (int k = 0; k < 27; k++) {
        int ox = c.y - k / 9;
        int oy = c.z - (k / 3) % 3;
        int oz = c.w - k % 3;
        unsigned rank = 0xFFFFFFFFu;
        if ((unsigned)ox < SXD && (unsigned)oy < SYD && (unsigned)oz < SZD) {
            unsigned lin = (unsigned)ox * YZ + (unsigned)oy * SZD + (unsigned)oz;
            unsigned word = lin >> 5;
            unsigned bpos = lin & 31;
            rank = __ldg(&g_pref[word]) +
                   __popc(__ldg(&g_bitmap[word]) & ((1u << bpos) - 1u));
            if ((__ldg(&g_coll[word]) >> bpos) & 1u) rank |= 0x80000000u;
        }
        g_rank[k * NPTS + n] = rank;
    }
}

__global__ void k_emit(float* __restrict__ uniqf) {
    unsigned i = blockIdx.x * blockDim.x + threadIdx.x;
    if (i >= WORDS) return;
    unsigned bits = g_bitmap[i];
    if (!bits) return;
    unsigned r = g_pref[i];
    unsigned vbase = i << 5;
    while (bits) {
        unsigned b = __ffs(bits) - 1u;
        bits &= bits - 1u;
        uniqf[r++] = (float)(vbase + b);
    }
}

// ---- persistent fp16-split HMMA GEMM + collision-split scatter (3 CTA/SM) ----
__global__ void __launch_bounds__(256, 3) k_gemm(
    const float4* __restrict__ feats4, float* __restrict__ out,
    const float4* __restrict__ bias4)
{
    extern __shared__ char smem[];
    uint32_t sb = smem_u32(smem);
    int tid = threadIdx.x;
    int wid = tid >> 5;
    int lane = tid & 31;
    int khalf = blockIdx.x & 1;
    int stream = blockIdx.x >> 1;
    int kbeg = khalf ? KB0 : 0;
    int kend = khalf ? 27 : KB0;

    // stage B (fp16) for our k-range ONCE
    {
        int nu4 = (kend - kbeg) * 144;
        const uint4* bh = reinterpret_cast<const uint4*>(g_Bh) + kbeg * 144;
        uint4* dh = reinterpret_cast<uint4*>(smem + BH_OFF);
        for (int i = tid; i < nu4; i += 256)
            dh[i] = __ldg(&bh[i]);
    }

    char* ebuf = smem + wid * 1024;             // 16 rows x 64B (aliases A region)
    uint32_t bl_lane = (unsigned)(lane & 7) * 144u + ((unsigned)(lane >> 3) & 1u) * 16u;
    float4 bq = __ldg(&bias4[lane & 3]);        // bias quarter for this lane's q

    for (int tile = stream; tile < NT; tile += NSTREAM) {
        int base_n = tile * TILEM;
        __syncthreads();                        // prev tile's ebuf done; B stage done

        // stage A tile (128 rows) as fp16 hi/lo
        for (int i = tid; i < 2048; i += 256) {
            int r = i >> 4, col = i & 15;
            int n = base_n + r;
            float4 f = (n < NPTS) ? __ldg(&feats4[(size_t)n * 16 + col])
                                  : make_float4(0.f, 0.f, 0.f, 0.f);
            __half h0 = __float2half_rn(f.x), h1 = __float2half_rn(f.y);
            __half h2 = __float2half_rn(f.z), h3 = __float2half_rn(f.w);
            __half l0 = __float2half_rn(f.x - __half2float(h0));
            __half l1 = __float2half_rn(f.y - __half2float(h1));
            __half l2 = __float2half_rn(f.z - __half2float(h2));
            __half l3 = __float2half_rn(f.w - __half2float(h3));
            uint2 hv, lv;
            hv.x = (unsigned)reinterpret_cast<unsigned short&>(h0) |
                   ((unsigned)reinterpret_cast<unsigned short&>(h1) << 16);
            hv.y = (unsigned)reinterpret_cast<unsigned short&>(h2) |
                   ((unsigned)reinterpret_cast<unsigned short&>(h3) << 16);
            lv.x = (unsigned)reinterpret_cast<unsigned short&>(l0) |
                   ((unsigned)reinterpret_cast<unsigned short&>(l1) << 16);
            lv.y = (unsigned)reinterpret_cast<unsigned short&>(l2) |
                   ((unsigned)reinterpret_cast<unsigned short&>(l3) << 16);
            unsigned off = (unsigned)r * 144u + (unsigned)col * 8u;
            *reinterpret_cast<uint2*>(smem + AH_OFF + off) = hv;
            *reinterpret_cast<uint2*>(smem + AL_OFF + off) = lv;
        }
        __syncthreads();

        // per-warp A fragments (16 rows)
        uint32_t ah[4][4], al[4][4];
        {
            uint32_t abase = sb + AH_OFF + (unsigned)(wid * 16 + (lane & 15)) * 144u
                           + ((unsigned)(lane >> 4) & 1u) * 16u;
#pragma unroll
            for (int kk = 0; kk < 4; kk++) {
                uint32_t a0 = abase + kk * 32u;
                asm volatile("ldmatrix.sync.aligned.m8n8.x4.shared.b16 {%0,%1,%2,%3},[%4];"
                    : "=r"(ah[kk][0]), "=r"(ah[kk][1]), "=r"(ah[kk][2]), "=r"(ah[kk][3]) : "r"(a0));
                uint32_t a1 = a0 + (AL_OFF - AH_OFF);
                asm volatile("ldmatrix.sync.aligned.m8n8.x4.shared.b16 {%0,%1,%2,%3},[%4];"
                    : "=r"(al[kk][0]), "=r"(al[kk][1]), "=r"(al[kk][2]), "=r"(al[kk][3]) : "r"(a1));
            }
        }
        __syncthreads();                        // all frags read before ebuf writes

#pragma unroll 1
        for (int k = kbeg; k < kend; k++) {
            // coalesced rank load (lanes 0..15 hold rows) — guarded
            unsigned rank = 0xFFFFFFFFu;
            int rown = base_n + wid * 16 + lane;
            if (lane < 16 && rown < NPTS)
                rank = __ldg(&g_rank[(size_t)k * NPTS + rown]);

            // B fragments for this k, loaded once
            uint32_t bh[4][2][2];
            uint32_t bk = sb + BH_OFF + (unsigned)(k - kbeg) * 2304u + bl_lane;
#pragma unroll
            for (int kk = 0; kk < 4; kk++) {
#pragma unroll
                for (int n2 = 0; n2 < 2; n2++) {
                    uint32_t ba = bk + (unsigned)(n2 * 8) * 144u + (unsigned)kk * 32u;
                    asm volatile("ldmatrix.sync.aligned.m8n8.x2.shared.b16 {%0,%1},[%2];"
                                 : "=r"(bh[kk][n2][0]), "=r"(bh[kk][n2][1])
                                 : "r"(ba));
                }
            }

            float c[2][4];
#pragma unroll
            for (int n2 = 0; n2 < 2; n2++)
#pragma unroll
                for (int q = 0; q < 4; q++) c[n2][q] = 0.f;

#pragma unroll
            for (int kk = 0; kk < 4; kk++) {
#pragma unroll
                for (int n2 = 0; n2 < 2; n2++) {
                    MMA(c[n2], ah[kk], bh[kk][n2][0], bh[kk][n2][1]);
                    MMA(c[n2], al[kk], bh[kk][n2][0], bh[kk][n2][1]);
                }
            }

            __syncwarp();
            {
                int r0 = lane >> 2;
                int cb = (lane & 3) * 2;
#pragma unroll
                for (int n2 = 0; n2 < 2; n2++) {
                    int colb = n2 * 8 + cb;
                    *reinterpret_cast<float2*>(ebuf + r0 * 64 + colb * 4) =
                        make_float2(c[n2][0], c[n2][1]);
                    *reinterpret_cast<float2*>(ebuf + (r0 + 8) * 64 + colb * 4) =
                        make_float2(c[n2][2], c[n2][3]);
                }
            }
            __syncwarp();
#pragma unroll
            for (int j = 0; j < 2; j++) {
                int rw = j * 8 + (lane >> 2);
                int q = lane & 3;
                unsigned rr = __shfl_sync(0xffffffffu, rank, rw);
                if (rr != 0xFFFFFFFFu) {
                    float4 v = *reinterpret_cast<const float4*>(ebuf + rw * 64 + q * 16);
                    if (rr & 0x80000000u) {
                        asm volatile("red.global.add.v4.f32 [%0], {%1,%2,%3,%4};"
                                     :: "l"(out + (size_t)(rr & 0x7FFFFFFFu) * 16 + q * 4),
                                        "f"(v.x), "f"(v.y), "f"(v.z), "f"(v.w)
                                     : "memory");
                    } else {
                        float4 w = make_float4(v.x + bq.x, v.y + bq.y,
                                               v.z + bq.z, v.w + bq.w);
                        *reinterpret_cast<float4*>(out + (size_t)rr * 16 + q * 4) = w;
                    }
                }
            }
            __syncwarp();
        }
    }
}

// ---------------- launch ----------------
extern "C" void kernel_launch(void* const* d_in, const int* in_sizes, int n_in,
                              void* d_out, int out_size) {
    const float* feats = (const float*)d_in[0];
    const int*   coords = (const int*)d_in[1];
    const float* W = (const float*)d_in[2];
    const float* bias = (const float*)d_in[3];
    float* out = (float*)d_out;
    float* uniqf = out + (size_t)NKTOT * 16;

    cudaFuncSetAttribute(k_gemm, cudaFuncAttributeMaxDynamicSharedMemorySize, SMEM_SZ);

    k_zero<<<2 * ZBLK + 27, 256>>>(W);
    k_mark<<<(NPTS + 255) / 256, 256>>>((const int4*)coords);
    k_scan1<<<NPART, 256>>>();
    k_scan2<<<1, 512>>>();
    k_combo<<<NPART + FOB, 256>>>((float4*)out, (const float4*)bias, uniqf);
    k_rank<<<(NPTS + 255) / 256, 256>>>((const int4*)coords);
    k_gemm<<<2 * NSTREAM, 256, SMEM_SZ>>>((const float4*)feats, out, (const float4*)bias);
    k_emit<<<(WORDS + 255) / 256, 256>>>(uniqf);
}